// round 2
// baseline (speedup 1.0000x reference)
// Transformer encoder block (pre-LN, ViT-style) — Round 1 baseline, fp32 SGEMM.
// B=16, S=577, EMB=768, HEADS=12, DK=64, DFF=3072.
// Pipeline: LN1 -> Q/K/V gemms -> scores (q@k^T, unscaled) -> softmax ->
//           ctx (attn@v) -> WO gemm (+bias+residual) -> LN2 ->
//           W1 gemm (+bias+exact GELU) -> W2 gemm (+bias+residual -> d_out)

#include <cuda_runtime.h>
#include <math.h>

#define EMB   768
#define HEADS 12
#define DK    64
#define DFF   3072
#define BATCH 16
#define SEQ   577
#define NTOK  (BATCH * SEQ)          // 9232
#define NBH   (BATCH * HEADS)        // 192

// ---------------- scratch (device globals; no runtime allocation) ------------
__device__ float g_h  [NTOK * EMB];        // LN1 output
__device__ float g_q  [NTOK * EMB];
__device__ float g_k  [NTOK * EMB];
__device__ float g_v  [NTOK * EMB];
__device__ float g_sc [(size_t)NBH * SEQ * SEQ];   // scores / attn (in-place softmax)
__device__ float g_ctx[NTOK * EMB];
__device__ float g_x2 [NTOK * EMB];        // attn residual output
__device__ float g_h2 [NTOK * EMB];        // LN2 output
__device__ float g_ff1[NTOK * DFF];        // GELU(h2@w1+b)

// ---------------- LayerNorm: one block (256 thr) per row of 768 --------------
__global__ void __launch_bounds__(256) ln_kernel(
    const float* __restrict__ x, const float* __restrict__ g,
    const float* __restrict__ b, float* __restrict__ out)
{
    int row = blockIdx.x;
    const float* xr = x + (size_t)row * EMB;
    float* orow = out + (size_t)row * EMB;
    int tid = threadIdx.x;

    float v0 = xr[tid], v1 = xr[tid + 256], v2 = xr[tid + 512];
    float s = v0 + v1 + v2;

    __shared__ float red[8];
    #pragma unroll
    for (int o = 16; o; o >>= 1) s += __shfl_xor_sync(0xffffffffu, s, o);
    if ((tid & 31) == 0) red[tid >> 5] = s;
    __syncthreads();
    float tot = 0.f;
    #pragma unroll
    for (int i = 0; i < 8; i++) tot += red[i];
    float mu = tot * (1.0f / EMB);
    __syncthreads();

    float d0 = v0 - mu, d1 = v1 - mu, d2 = v2 - mu;
    float qv = d0 * d0 + d1 * d1 + d2 * d2;
    #pragma unroll
    for (int o = 16; o; o >>= 1) qv += __shfl_xor_sync(0xffffffffu, qv, o);
    if ((tid & 31) == 0) red[tid >> 5] = qv;
    __syncthreads();
    float tot2 = 0.f;
    #pragma unroll
    for (int i = 0; i < 8; i++) tot2 += red[i];
    float rstd = rsqrtf(tot2 * (1.0f / EMB) + 1e-5f);

    orow[tid]       = d0 * rstd * g[tid]       + b[tid];
    orow[tid + 256] = d1 * rstd * g[tid + 256] + b[tid + 256];
    orow[tid + 512] = d2 * rstd * g[tid + 512] + b[tid + 512];
}

// ---------------- dense GEMM: C[M,N] = A[M,K] @ W[K,N] + bias (+epi) ---------
// EPI: 0 = bias only, 1 = bias + exact GELU, 2 = bias + residual add
// Tiles: BM=BN=128, BK=8, 256 threads, 8x8 microtile per thread.
// Requires: N % 128 == 0, K % 8 == 0 (true for all call sites).
template <int EPI>
__global__ void __launch_bounds__(256) gemm_kernel(
    const float* __restrict__ A, const float* __restrict__ W,
    const float* __restrict__ bias, const float* __restrict__ res,
    float* __restrict__ C, int M, int N, int K)
{
    __shared__ float As[8][128];
    __shared__ float Bs[8][128];
    int tid = threadIdx.x;
    int m0 = blockIdx.y * 128;
    int n0 = blockIdx.x * 128;

    int a_row = tid >> 1;            // 0..127
    int a_seg = (tid & 1) << 2;      // 0 or 4
    int b_row = tid >> 5;            // 0..7
    int b_col = (tid & 31) << 2;     // 0..124
    int ty = tid >> 4, tx = tid & 15;

    float acc[8][8];
    #pragma unroll
    for (int i = 0; i < 8; i++)
        #pragma unroll
        for (int j = 0; j < 8; j++) acc[i][j] = 0.f;

    for (int k0 = 0; k0 < K; k0 += 8) {
        float4 av = make_float4(0.f, 0.f, 0.f, 0.f);
        int gm = m0 + a_row;
        if (gm < M)
            av = *reinterpret_cast<const float4*>(&A[(size_t)gm * K + k0 + a_seg]);
        As[a_seg + 0][a_row] = av.x;
        As[a_seg + 1][a_row] = av.y;
        As[a_seg + 2][a_row] = av.z;
        As[a_seg + 3][a_row] = av.w;

        float4 bv = *reinterpret_cast<const float4*>(&W[(size_t)(k0 + b_row) * N + n0 + b_col]);
        *reinterpret_cast<float4*>(&Bs[b_row][b_col]) = bv;
        __syncthreads();

        #pragma unroll
        for (int kk = 0; kk < 8; kk++) {
            float ar[8], br[8];
            #pragma unroll
            for (int i = 0; i < 8; i++) ar[i] = As[kk][ty * 8 + i];
            #pragma unroll
            for (int j = 0; j < 8; j++) br[j] = Bs[kk][tx * 8 + j];
            #pragma unroll
            for (int i = 0; i < 8; i++)
                #pragma unroll
                for (int j = 0; j < 8; j++) acc[i][j] += ar[i] * br[j];
        }
        __syncthreads();
    }

    #pragma unroll
    for (int i = 0; i < 8; i++) {
        int gm = m0 + ty * 8 + i;
        if (gm >= M) break;          // thread's rows are consecutive
        #pragma unroll
        for (int j = 0; j < 8; j++) {
            int gn = n0 + tx * 8 + j;
            float vv = acc[i][j] + bias[gn];
            if (EPI == 1) vv = 0.5f * vv * (1.0f + erff(vv * 0.70710678118654752f));
            if (EPI == 2) vv += res[(size_t)gm * N + gn];
            C[(size_t)gm * N + gn] = vv;
        }
    }
}

// ---------------- scores: per (b,h): S x S = q[S,64] @ k[S,64]^T --------------
// 64x64 tiles, BK=16, 256 threads, 4x4 microtile.
__global__ void __launch_bounds__(256) scores_kernel(
    const float* __restrict__ q, const float* __restrict__ k,
    float* __restrict__ scores)
{
    int bh = blockIdx.z;
    int b = bh / HEADS, h = bh % HEADS;
    const float* qb = q + (size_t)b * SEQ * EMB + h * DK;
    const float* kb = k + (size_t)b * SEQ * EMB + h * DK;
    float* sc = scores + (size_t)bh * SEQ * SEQ;
    int m0 = blockIdx.y * 64, n0 = blockIdx.x * 64;

    __shared__ float As[16][64];
    __shared__ float Bs[16][64];
    int tid = threadIdx.x;
    int l_row = tid >> 2;            // 0..63
    int l_seg = (tid & 3) << 2;      // 0,4,8,12
    int ty = tid >> 4, tx = tid & 15;

    float acc[4][4];
    #pragma unroll
    for (int i = 0; i < 4; i++)
        #pragma unroll
        for (int j = 0; j < 4; j++) acc[i][j] = 0.f;

    for (int k0 = 0; k0 < DK; k0 += 16) {
        float4 av = make_float4(0.f, 0.f, 0.f, 0.f);
        if (m0 + l_row < SEQ)
            av = *reinterpret_cast<const float4*>(&qb[(size_t)(m0 + l_row) * EMB + k0 + l_seg]);
        As[l_seg + 0][l_row] = av.x;
        As[l_seg + 1][l_row] = av.y;
        As[l_seg + 2][l_row] = av.z;
        As[l_seg + 3][l_row] = av.w;

        float4 bv = make_float4(0.f, 0.f, 0.f, 0.f);
        if (n0 + l_row < SEQ)
            bv = *reinterpret_cast<const float4*>(&kb[(size_t)(n0 + l_row) * EMB + k0 + l_seg]);
        Bs[l_seg + 0][l_row] = bv.x;
        Bs[l_seg + 1][l_row] = bv.y;
        Bs[l_seg + 2][l_row] = bv.z;
        Bs[l_seg + 3][l_row] = bv.w;
        __syncthreads();

        #pragma unroll
        for (int kk = 0; kk < 16; kk++) {
            float ar[4], br[4];
            #pragma unroll
            for (int i = 0; i < 4; i++) ar[i] = As[kk][ty * 4 + i];
            #pragma unroll
            for (int j = 0; j < 4; j++) br[j] = Bs[kk][tx * 4 + j];
            #pragma unroll
            for (int i = 0; i < 4; i++)
                #pragma unroll
                for (int j = 0; j < 4; j++) acc[i][j] += ar[i] * br[j];
        }
        __syncthreads();
    }

    #pragma unroll
    for (int i = 0; i < 4; i++) {
        int gm = m0 + ty * 4 + i;
        if (gm >= SEQ) break;
        #pragma unroll
        for (int j = 0; j < 4; j++) {
            int gn = n0 + tx * 4 + j;
            if (gn < SEQ) sc[(size_t)gm * SEQ + gn] = acc[i][j];
        }
    }
}

// ---------------- softmax over last dim (577), in place ----------------------
__global__ void __launch_bounds__(128) softmax_kernel(float* __restrict__ scores)
{
    size_t row = blockIdx.x;
    float* r = scores + row * SEQ;
    int tid = threadIdx.x;

    float vals[5];
    float mx = -1e30f;
    #pragma unroll
    for (int i = 0; i < 5; i++) {
        int c = tid + i * 128;
        vals[i] = (c < SEQ) ? r[c] : -1e30f;
        mx = fmaxf(mx, vals[i]);
    }
    __shared__ float sm[4];
    #pragma unroll
    for (int o = 16; o; o >>= 1) mx = fmaxf(mx, __shfl_xor_sync(0xffffffffu, mx, o));
    if ((tid & 31) == 0) sm[tid >> 5] = mx;
    __syncthreads();
    mx = fmaxf(fmaxf(sm[0], sm[1]), fmaxf(sm[2], sm[3]));
    __syncthreads();

    float s = 0.f;
    #pragma unroll
    for (int i = 0; i < 5; i++) {
        int c = tid + i * 128;
        vals[i] = (c < SEQ) ? __expf(vals[i] - mx) : 0.f;
        s += vals[i];
    }
    #pragma unroll
    for (int o = 16; o; o >>= 1) s += __shfl_xor_sync(0xffffffffu, s, o);
    if ((tid & 31) == 0) sm[tid >> 5] = s;
    __syncthreads();
    float inv = 1.0f / (sm[0] + sm[1] + sm[2] + sm[3]);

    #pragma unroll
    for (int i = 0; i < 5; i++) {
        int c = tid + i * 128;
        if (c < SEQ) r[c] = vals[i] * inv;
    }
}

// ---------------- ctx: per (b,h): [S,64] = attn[S,S] @ v[S,64] ---------------
// BM=64, BN=64 (full DK), BK=32, 256 threads, 4x4 microtile.
__global__ void __launch_bounds__(256) ctx_kernel(
    const float* __restrict__ attn, const float* __restrict__ v,
    float* __restrict__ ctx)
{
    int bh = blockIdx.y;
    int b = bh / HEADS, h = bh % HEADS;
    const float* ab = attn + (size_t)bh * SEQ * SEQ;
    const float* vb = v + (size_t)b * SEQ * EMB + h * DK;
    float* cb = ctx + (size_t)b * SEQ * EMB + h * DK;
    int m0 = blockIdx.x * 64;

    __shared__ float As[64][33];   // attn tile [m][k], padded
    __shared__ float Bs[32][64];   // v tile [k][d]
    int tid = threadIdx.x;
    int ty = tid >> 4, tx = tid & 15;

    float acc[4][4];
    #pragma unroll
    for (int i = 0; i < 4; i++)
        #pragma unroll
        for (int j = 0; j < 4; j++) acc[i][j] = 0.f;

    for (int k0 = 0; k0 < SEQ; k0 += 32) {
        #pragma unroll
        for (int i = 0; i < 8; i++) {         // 64*32 scalars / 256 thr
            int l = tid + i * 256;
            int rr = l >> 5, cc = l & 31;
            float val = 0.f;
            if (m0 + rr < SEQ && k0 + cc < SEQ)
                val = ab[(size_t)(m0 + rr) * SEQ + (k0 + cc)];
            As[rr][cc] = val;
        }
        #pragma unroll
        for (int i = 0; i < 2; i++) {         // 32*64 floats = 512 float4
            int l = tid + i * 256;
            int rr = l >> 4, c4 = (l & 15) << 2;
            float4 bv = make_float4(0.f, 0.f, 0.f, 0.f);
            if (k0 + rr < SEQ)
                bv = *reinterpret_cast<const float4*>(&vb[(size_t)(k0 + rr) * EMB + c4]);
            *reinterpret_cast<float4*>(&Bs[rr][c4]) = bv;
        }
        __syncthreads();

        #pragma unroll
        for (int kk = 0; kk < 32; kk++) {
            float ar[4], br[4];
            #pragma unroll
            for (int i = 0; i < 4; i++) ar[i] = As[ty * 4 + i][kk];
            #pragma unroll
            for (int j = 0; j < 4; j++) br[j] = Bs[kk][tx * 4 + j];
            #pragma unroll
            for (int i = 0; i < 4; i++)
                #pragma unroll
                for (int j = 0; j < 4; j++) acc[i][j] += ar[i] * br[j];
        }
        __syncthreads();
    }

    #pragma unroll
    for (int i = 0; i < 4; i++) {
        int gm = m0 + ty * 4 + i;
        if (gm >= SEQ) break;
        #pragma unroll
        for (int j = 0; j < 4; j++)
            cb[(size_t)gm * EMB + tx * 4 + j] = acc[i][j];
    }
}

// ---------------- host orchestration ----------------------------------------
extern "C" void kernel_launch(void* const* d_in, const int* in_sizes, int n_in,
                              void* d_out, int out_size)
{
    const float* x     = (const float*)d_in[0];
    const float* wq    = (const float*)d_in[1];
    const float* bq    = (const float*)d_in[2];
    const float* wk    = (const float*)d_in[3];
    const float* bk    = (const float*)d_in[4];
    const float* wv    = (const float*)d_in[5];
    const float* bv    = (const float*)d_in[6];
    const float* wo    = (const float*)d_in[7];
    const float* bo    = (const float*)d_in[8];
    const float* w1    = (const float*)d_in[9];
    const float* bf1   = (const float*)d_in[10];
    const float* w2    = (const float*)d_in[11];
    const float* bf2   = (const float*)d_in[12];
    const float* ln1_g = (const float*)d_in[13];
    const float* ln1_b = (const float*)d_in[14];
    const float* ln2_g = (const float*)d_in[15];
    const float* ln2_b = (const float*)d_in[16];
    float* out = (float*)d_out;

    float *h, *q, *k, *v, *sc, *ctx, *x2, *h2, *ff1;
    cudaGetSymbolAddress((void**)&h,   g_h);
    cudaGetSymbolAddress((void**)&q,   g_q);
    cudaGetSymbolAddress((void**)&k,   g_k);
    cudaGetSymbolAddress((void**)&v,   g_v);
    cudaGetSymbolAddress((void**)&sc,  g_sc);
    cudaGetSymbolAddress((void**)&ctx, g_ctx);
    cudaGetSymbolAddress((void**)&x2,  g_x2);
    cudaGetSymbolAddress((void**)&h2,  g_h2);
    cudaGetSymbolAddress((void**)&ff1, g_ff1);

    const int M = NTOK;                        // 9232
    dim3 g768(EMB / 128, (M + 127) / 128);     // (6, 73)
    dim3 g3072(DFF / 128, (M + 127) / 128);    // (24, 73)

    // LN1
    ln_kernel<<<M, 256>>>(x, ln1_g, ln1_b, h);
    // Q, K, V projections
    gemm_kernel<0><<<g768, 256>>>(h, wq, bq, nullptr, q, M, EMB, EMB);
    gemm_kernel<0><<<g768, 256>>>(h, wk, bk, nullptr, k, M, EMB, EMB);
    gemm_kernel<0><<<g768, 256>>>(h, wv, bv, nullptr, v, M, EMB, EMB);
    // attention
    scores_kernel<<<dim3(10, 10, NBH), 256>>>(q, k, sc);
    softmax_kernel<<<NBH * SEQ, 128>>>(sc);
    ctx_kernel<<<dim3(10, NBH), 256>>>(sc, v, ctx);
    // output projection + residual
    gemm_kernel<2><<<g768, 256>>>(ctx, wo, bo, x, x2, M, EMB, EMB);
    // LN2 + FFN
    ln_kernel<<<M, 256>>>(x2, ln2_g, ln2_b, h2);
    gemm_kernel<1><<<g3072, 256>>>(h2, w1, bf1, nullptr, ff1, M, DFF, EMB);
    gemm_kernel<2><<<g768, 256>>>(ff1, w2, bf2, x2, out, M, EMB, DFF);
}

// round 6
// speedup vs baseline: 3.2094x; 3.2094x over previous
// Transformer encoder block — Round 3: mma.sync tf32 tensor-core GEMMs.
// (tcgen05 unavailable: harness PTX target is plain sm_103.)
// B=16, S=577, EMB=768, HEADS=12, DK=64, DFF=3072.

#include <cuda_runtime.h>
#include <cstdint>
#include <math.h>

#define EMB   768
#define HEADS 12
#define DK    64
#define DFF   3072
#define BATCH 16
#define SEQ   577
#define SEQP  600                     // padded score row stride
#define NTOK  (BATCH * SEQ)           // 9232
#define NBH   (BATCH * HEADS)         // 192
#define QKVW  (3 * EMB)               // 2304

// ---------------- scratch (device globals) -----------------------------------
__device__ float g_h   [NTOK * EMB];
__device__ float g_qkv [(size_t)NTOK * QKVW];
__device__ float g_vT  [(size_t)NBH * DK * SEQP];
__device__ float g_sc  [(size_t)NBH * SEQ * SEQP];
__device__ float g_ctx [NTOK * EMB];
__device__ float g_x2  [NTOK * EMB];
__device__ float g_h2  [NTOK * EMB];
__device__ float g_ff1 [(size_t)NTOK * DFF];
__device__ float g_wqkvT[QKVW * EMB];
__device__ float g_woT [EMB * EMB];
__device__ float g_w1T [DFF * EMB];
__device__ float g_w2T [EMB * DFF];
__device__ float g_bqkv[QKVW];

// ---------------- PTX helpers -------------------------------------------------
__device__ __forceinline__ uint32_t smem_u32(const void* p) {
    uint32_t a;
    asm("{ .reg .u64 t; cvta.to.shared.u64 t, %1; cvt.u32.u64 %0, t; }"
        : "=r"(a) : "l"(p));
    return a;
}
__device__ __forceinline__ float rnd_tf32(float x) {
    float r;
    asm("cvt.rna.tf32.f32 %0, %1;" : "=f"(r) : "f"(x));
    return r;
}
__device__ __forceinline__ void cp_async16(uint32_t dst, const void* src, int srcBytes) {
    asm volatile("cp.async.cg.shared.global [%0], [%1], 16, %2;"
                 :: "r"(dst), "l"(src), "r"(srcBytes) : "memory");
}
__device__ __forceinline__ void cp_commit() {
    asm volatile("cp.async.commit_group;" ::: "memory");
}
template <int N> __device__ __forceinline__ void cp_wait() {
    asm volatile("cp.async.wait_group %0;" :: "n"(N) : "memory");
}
__device__ __forceinline__ void mma_tf32(float* d, const uint32_t* a, const uint32_t* b) {
    asm volatile(
        "mma.sync.aligned.m16n8k8.row.col.f32.tf32.tf32.f32 "
        "{%0,%1,%2,%3}, {%4,%5,%6,%7}, {%8,%9}, {%0,%1,%2,%3};"
        : "+f"(d[0]), "+f"(d[1]), "+f"(d[2]), "+f"(d[3])
        : "r"(a[0]), "r"(a[1]), "r"(a[2]), "r"(a[3]), "r"(b[0]), "r"(b[1]));
}

// ---------------- generic tf32 mma.sync GEMM ----------------------------------
// C[z][M,N] = A[z][M,K] @ B[z][N,K]^T  (+bias)(+GELU)(+res)(round)
// BM=128, BK=32, BN in {64,128}. 256 threads, 3-stage cp.async pipeline.
// SMEM: A[128][36], B[BN][36] per stage (stride 36 -> conflict-free frag loads).
template <int BN, bool BIAS, bool GELU, bool RES, bool RND>
__global__ void __launch_bounds__(256) tcgemm(
    const float* __restrict__ A, const float* __restrict__ B,
    const float* __restrict__ bias, const float* __restrict__ res,
    float* __restrict__ C, int M, int N, int K,
    int lda, int ldb, int ldc,
    long sAb, long sAh, long sBb, long sBh, long sCb, long sCh)
{
    constexpr int WROWS = (BN >= 128) ? 2 : 4;
    constexpr int WCOLS = 8 / WROWS;
    constexpr int WM = 128 / WROWS;        // 64 or 32
    constexpr int WN = BN / WCOLS;         // 32
    constexpr int MT = WM / 16;            // 4 or 2
    constexpr int NT = WN / 8;             // 4
    constexpr int SA = 36;                 // floats per smem row
    constexpr int ASTGF = 128 * SA;
    constexpr int BSTGF = BN * SA;
    constexpr int STGF  = ASTGF + BSTGF;

    extern __shared__ float smem[];
    const uint32_t sb = smem_u32(smem);
    const int tid = threadIdx.x;
    const int wid = tid >> 5, lane = tid & 31;
    const int g = lane >> 2, tig = lane & 3;
    const int wr = wid / WCOLS, wc = wid % WCOLS;
    const int wm0 = wr * WM, wn0 = wc * WN;

    const int zb = blockIdx.z / HEADS, zh = blockIdx.z % HEADS;
    const float* Az = A + zb * sAb + zh * sAh;
    const float* Bz = B + zb * sBb + zh * sBh;
    float* Cz = C + zb * sCb + zh * sCh;
    const float* Rz = RES ? (res + zb * sCb + zh * sCh) : nullptr;
    const int m0 = blockIdx.y * 128, n0 = blockIdx.x * BN;

    const int nCh = (K + 31) >> 5;

    auto loadA = [&](int c, int buf) {
        uint32_t base = sb + (uint32_t)(buf * STGF) * 4u;
        int k0 = c << 5;
        #pragma unroll
        for (int i = 0; i < 4; i++) {
            int s = tid + i * 256, r = s >> 3, sg = s & 7;
            int gm = m0 + r, kb = k0 + sg * 4;
            int bytes = 0;
            if (gm < M) { int rem = (K - kb) * 4; bytes = rem >= 16 ? 16 : (rem > 0 ? rem : 0); }
            const float* src = Az + (size_t)(gm < M ? gm : 0) * lda + (kb < K ? kb : 0);
            cp_async16(base + (uint32_t)(r * SA * 4 + sg * 16), src, bytes);
        }
    };
    auto loadB = [&](int c, int buf) {
        uint32_t base = sb + (uint32_t)(buf * STGF + ASTGF) * 4u;
        int k0 = c << 5;
        #pragma unroll
        for (int i = 0; i < BN / 32; i++) {
            int s = tid + i * 256, r = s >> 3, sg = s & 7;
            int gn = n0 + r, kb = k0 + sg * 4;
            int bytes = 0;
            if (gn < N) { int rem = (K - kb) * 4; bytes = rem >= 16 ? 16 : (rem > 0 ? rem : 0); }
            const float* src = Bz + (size_t)(gn < N ? gn : 0) * ldb + (kb < K ? kb : 0);
            cp_async16(base + (uint32_t)(r * SA * 4 + sg * 16), src, bytes);
        }
    };

    float acc[MT][NT][4];
    #pragma unroll
    for (int i = 0; i < MT; i++)
        #pragma unroll
        for (int j = 0; j < NT; j++)
            #pragma unroll
            for (int q = 0; q < 4; q++) acc[i][j][q] = 0.f;

    loadA(0, 0); loadB(0, 0); cp_commit();
    if (1 < nCh) { loadA(1, 1); loadB(1, 1); } cp_commit();

    for (int c = 0; c < nCh; c++) {
        int buf = c % 3;
        cp_wait<1>();
        __syncthreads();
        int p = c + 2;
        if (p < nCh) { loadA(p, p % 3); loadB(p, p % 3); }
        cp_commit();

        const float* Asf = smem + buf * STGF;
        const float* Bsf = Asf + ASTGF;
        #pragma unroll
        for (int ks = 0; ks < 4; ks++) {
            const int k = ks * 8;
            uint32_t af[MT][4], bf[NT][2];
            #pragma unroll
            for (int mt = 0; mt < MT; mt++) {
                const float* ap = Asf + (wm0 + mt * 16 + g) * SA + k + tig;
                af[mt][0] = __float_as_uint(ap[0]);
                af[mt][1] = __float_as_uint(ap[8 * SA]);
                af[mt][2] = __float_as_uint(ap[4]);
                af[mt][3] = __float_as_uint(ap[8 * SA + 4]);
            }
            #pragma unroll
            for (int nt = 0; nt < NT; nt++) {
                const float* bp = Bsf + (wn0 + nt * 8 + g) * SA + k + tig;
                bf[nt][0] = __float_as_uint(bp[0]);
                bf[nt][1] = __float_as_uint(bp[4]);
            }
            #pragma unroll
            for (int mt = 0; mt < MT; mt++)
                #pragma unroll
                for (int nt = 0; nt < NT; nt++)
                    mma_tf32(acc[mt][nt], af[mt], bf[nt]);
        }
    }

    // ------- epilogue: fragments -> global (float2), fused bias/gelu/res/rnd
    #pragma unroll
    for (int mt = 0; mt < MT; mt++) {
        #pragma unroll
        for (int nt = 0; nt < NT; nt++) {
            int gm = m0 + wm0 + mt * 16 + g;
            int gn = n0 + wn0 + nt * 8 + 2 * tig;
            #pragma unroll
            for (int half = 0; half < 2; half++) {
                int gmr = gm + half * 8;
                if (gmr >= M) continue;
                float v0 = acc[mt][nt][half * 2 + 0];
                float v1 = acc[mt][nt][half * 2 + 1];
                if (BIAS) { v0 += bias[gn]; v1 += (gn + 1 < N) ? bias[gn + 1] : 0.f; }
                if (GELU) {
                    v0 = 0.5f * v0 * (1.0f + erff(v0 * 0.7071067811865475f));
                    v1 = 0.5f * v1 * (1.0f + erff(v1 * 0.7071067811865475f));
                }
                float* crow = Cz + (size_t)gmr * ldc;
                if (RES) {
                    const float* rrow = Rz + (size_t)gmr * ldc;
                    v0 += rrow[gn];
                    if (gn + 1 < N) v1 += rrow[gn + 1];
                }
                if (RND) { v0 = rnd_tf32(v0); v1 = rnd_tf32(v1); }
                if (gn + 1 < N) {
                    *reinterpret_cast<float2*>(crow + gn) = make_float2(v0, v1);
                } else if (gn < N) {
                    crow[gn] = v0;
                }
            }
        }
    }
}

// ---------------- LayerNorm (tf32-rounded output) -----------------------------
__global__ void __launch_bounds__(256) ln_kernel(
    const float* __restrict__ x, const float* __restrict__ g,
    const float* __restrict__ b, float* __restrict__ out)
{
    int row = blockIdx.x;
    const float* xr = x + (size_t)row * EMB;
    float* orow = out + (size_t)row * EMB;
    int tid = threadIdx.x;

    float v0 = xr[tid], v1 = xr[tid + 256], v2 = xr[tid + 512];
    float s = v0 + v1 + v2;
    __shared__ float red[8];
    #pragma unroll
    for (int o = 16; o; o >>= 1) s += __shfl_xor_sync(0xffffffffu, s, o);
    if ((tid & 31) == 0) red[tid >> 5] = s;
    __syncthreads();
    float tot = 0.f;
    #pragma unroll
    for (int i = 0; i < 8; i++) tot += red[i];
    float mu = tot * (1.0f / EMB);
    __syncthreads();
    float d0 = v0 - mu, d1 = v1 - mu, d2 = v2 - mu;
    float qv = d0 * d0 + d1 * d1 + d2 * d2;
    #pragma unroll
    for (int o = 16; o; o >>= 1) qv += __shfl_xor_sync(0xffffffffu, qv, o);
    if ((tid & 31) == 0) red[tid >> 5] = qv;
    __syncthreads();
    float tot2 = 0.f;
    #pragma unroll
    for (int i = 0; i < 8; i++) tot2 += red[i];
    float rstd = rsqrtf(tot2 * (1.0f / EMB) + 1e-5f);

    orow[tid]       = rnd_tf32(d0 * rstd * g[tid]       + b[tid]);
    orow[tid + 256] = rnd_tf32(d1 * rstd * g[tid + 256] + b[tid + 256]);
    orow[tid + 512] = rnd_tf32(d2 * rstd * g[tid + 512] + b[tid + 512]);
}

// ---------------- softmax over last dim (577), stride SEQP, tf32-rounded ------
__global__ void __launch_bounds__(128) softmax_kernel(float* __restrict__ scores)
{
    float* r = scores + (size_t)blockIdx.x * SEQP;
    int tid = threadIdx.x;
    float vals[5];
    float mx = -1e30f;
    #pragma unroll
    for (int i = 0; i < 5; i++) {
        int c = tid + i * 128;
        vals[i] = (c < SEQ) ? r[c] : -1e30f;
        mx = fmaxf(mx, vals[i]);
    }
    __shared__ float sm[4];
    #pragma unroll
    for (int o = 16; o; o >>= 1) mx = fmaxf(mx, __shfl_xor_sync(0xffffffffu, mx, o));
    if ((tid & 31) == 0) sm[tid >> 5] = mx;
    __syncthreads();
    mx = fmaxf(fmaxf(sm[0], sm[1]), fmaxf(sm[2], sm[3]));
    __syncthreads();
    float s = 0.f;
    #pragma unroll
    for (int i = 0; i < 5; i++) {
        int c = tid + i * 128;
        vals[i] = (c < SEQ) ? __expf(vals[i] - mx) : 0.f;
        s += vals[i];
    }
    #pragma unroll
    for (int o = 16; o; o >>= 1) s += __shfl_xor_sync(0xffffffffu, s, o);
    if ((tid & 31) == 0) sm[tid >> 5] = s;
    __syncthreads();
    float inv = 1.0f / (sm[0] + sm[1] + sm[2] + sm[3]);
    #pragma unroll
    for (int i = 0; i < 5; i++) {
        int c = tid + i * 128;
        if (c < SEQ) r[c] = rnd_tf32(vals[i] * inv);
    }
}

// ---------------- weight transpose + tf32 round -------------------------------
__global__ void __launch_bounds__(256) transpose_rnd(
    const float* __restrict__ in, float* __restrict__ out, int K, int N)
{
    __shared__ float t[32][33];
    int bx = blockIdx.x * 32;   // n
    int by = blockIdx.y * 32;   // k
    int tx = threadIdx.x & 31, ty = threadIdx.x >> 5;
    #pragma unroll
    for (int i = 0; i < 32; i += 8)
        t[ty + i][tx] = in[(size_t)(by + ty + i) * N + bx + tx];
    __syncthreads();
    #pragma unroll
    for (int i = 0; i < 32; i += 8)
        out[(size_t)(bx + ty + i) * K + by + tx] = rnd_tf32(t[tx][ty + i]);
}

// ---------------- v head transpose --------------------------------------------
__global__ void __launch_bounds__(256) vtrans_kernel(
    const float* __restrict__ qkv, float* __restrict__ vT)
{
    int z = blockIdx.z, b = z / HEADS, h = z % HEADS;
    int s0 = blockIdx.x * 32, d0 = blockIdx.y * 32;
    __shared__ float t[32][33];
    int tx = threadIdx.x & 31, ty = threadIdx.x >> 5;
    const float* src = qkv + (size_t)b * SEQ * QKVW + 2 * EMB + h * DK;
    #pragma unroll
    for (int i = 0; i < 32; i += 8) {
        int s = s0 + ty + i;
        t[ty + i][tx] = (s < SEQ) ? src[(size_t)s * QKVW + d0 + tx] : 0.f;
    }
    __syncthreads();
    float* dst = vT + ((size_t)z * DK + d0) * SEQP + s0;
    #pragma unroll
    for (int i = 0; i < 32; i += 8) {
        if (s0 + tx < SEQ) dst[(size_t)(ty + i) * SEQP + tx] = t[tx][ty + i];
    }
}

__global__ void concat_bias(const float* __restrict__ bq, const float* __restrict__ bk,
                            const float* __restrict__ bv, float* __restrict__ o)
{
    int i = blockIdx.x * 256 + threadIdx.x;
    if (i < EMB) { o[i] = bq[i]; o[i + EMB] = bk[i]; o[i + 2 * EMB] = bv[i]; }
}

// ---------------- host orchestration ------------------------------------------
extern "C" void kernel_launch(void* const* d_in, const int* in_sizes, int n_in,
                              void* d_out, int out_size)
{
    const float* x     = (const float*)d_in[0];
    const float* wq    = (const float*)d_in[1];
    const float* bq    = (const float*)d_in[2];
    const float* wk    = (const float*)d_in[3];
    const float* bk    = (const float*)d_in[4];
    const float* wv    = (const float*)d_in[5];
    const float* bv    = (const float*)d_in[6];
    const float* wo    = (const float*)d_in[7];
    const float* bo    = (const float*)d_in[8];
    const float* w1    = (const float*)d_in[9];
    const float* bf1   = (const float*)d_in[10];
    const float* w2    = (const float*)d_in[11];
    const float* bf2   = (const float*)d_in[12];
    const float* ln1_g = (const float*)d_in[13];
    const float* ln1_b = (const float*)d_in[14];
    const float* ln2_g = (const float*)d_in[15];
    const float* ln2_b = (const float*)d_in[16];
    float* out = (float*)d_out;

    float *h, *qkv, *vT, *sc, *ctx, *x2, *h2, *ff1;
    float *wqkvT, *woT, *w1T, *w2T, *bqkv;
    cudaGetSymbolAddress((void**)&h,     g_h);
    cudaGetSymbolAddress((void**)&qkv,   g_qkv);
    cudaGetSymbolAddress((void**)&vT,    g_vT);
    cudaGetSymbolAddress((void**)&sc,    g_sc);
    cudaGetSymbolAddress((void**)&ctx,   g_ctx);
    cudaGetSymbolAddress((void**)&x2,    g_x2);
    cudaGetSymbolAddress((void**)&h2,    g_h2);
    cudaGetSymbolAddress((void**)&ff1,   g_ff1);
    cudaGetSymbolAddress((void**)&wqkvT, g_wqkvT);
    cudaGetSymbolAddress((void**)&woT,   g_woT);
    cudaGetSymbolAddress((void**)&w1T,   g_w1T);
    cudaGetSymbolAddress((void**)&w2T,   g_w2T);
    cudaGetSymbolAddress((void**)&bqkv,  g_bqkv);

    // dynamic smem: 3 stages of (128 + BN) rows * 36 floats
    const int SM128 = 3 * (128 + 128) * 36 * 4;   // 110592
    const int SM64  = 3 * (128 + 64)  * 36 * 4;   //  82944
    cudaFuncSetAttribute(tcgemm<128, true,  false, false, true >, cudaFuncAttributeMaxDynamicSharedMemorySize, SM128);
    cudaFuncSetAttribute(tcgemm<128, false, false, false, false>, cudaFuncAttributeMaxDynamicSharedMemorySize, SM128);
    cudaFuncSetAttribute(tcgemm<64,  false, false, false, true >, cudaFuncAttributeMaxDynamicSharedMemorySize, SM64);
    cudaFuncSetAttribute(tcgemm<128, true,  false, true,  false>, cudaFuncAttributeMaxDynamicSharedMemorySize, SM128);
    cudaFuncSetAttribute(tcgemm<128, true,  true,  false, true >, cudaFuncAttributeMaxDynamicSharedMemorySize, SM128);

    const int M = NTOK;
    const int MT_ = (M + 127) / 128;       // 73
    const int ST_ = (SEQ + 127) / 128;     // 5
    const long SS = (long)SEQ * SEQP;

    // weight prep (deterministic each call)
    transpose_rnd<<<dim3(EMB / 32, EMB / 32), 256>>>(wq, wqkvT,                 EMB, EMB);
    transpose_rnd<<<dim3(EMB / 32, EMB / 32), 256>>>(wk, wqkvT + EMB * EMB,     EMB, EMB);
    transpose_rnd<<<dim3(EMB / 32, EMB / 32), 256>>>(wv, wqkvT + 2 * EMB * EMB, EMB, EMB);
    transpose_rnd<<<dim3(EMB / 32, EMB / 32), 256>>>(wo, woT, EMB, EMB);
    transpose_rnd<<<dim3(DFF / 32, EMB / 32), 256>>>(w1, w1T, EMB, DFF);
    transpose_rnd<<<dim3(EMB / 32, DFF / 32), 256>>>(w2, w2T, DFF, EMB);
    concat_bias<<<3, 256>>>(bq, bk, bv, bqkv);

    // LN1
    ln_kernel<<<M, 256>>>(x, ln1_g, ln1_b, h);

    // fused QKV: [9232, 2304] = h @ wqkvT^T   (+bias, round)
    tcgemm<128, true, false, false, true><<<dim3(QKVW / 128, MT_, 1), 256, SM128>>>(
        h, wqkvT, bqkv, nullptr, qkv, M, QKVW, EMB, EMB, EMB, QKVW,
        0, 0, 0, 0, 0, 0);

    // v transpose per head
    vtrans_kernel<<<dim3((SEQ + 31) / 32, DK / 32, NBH), 256>>>(qkv, vT);

    // scores: per (b,h) 577x577 = q @ k^T  (K = 64)
    tcgemm<128, false, false, false, false><<<dim3(ST_, ST_, NBH), 256, SM128>>>(
        qkv, qkv + EMB, nullptr, nullptr, sc,
        SEQ, SEQ, DK, QKVW, QKVW, SEQP,
        (long)SEQ * QKVW, DK, (long)SEQ * QKVW, DK, (long)HEADS * SS, SS);

    // softmax
    softmax_kernel<<<NBH * SEQ, 128>>>(sc);

    // ctx: per (b,h) [577, 64] = attn @ vT^T  (K = 577, round)
    tcgemm<64, false, false, false, true><<<dim3(1, ST_, NBH), 256, SM64>>>(
        sc, vT, nullptr, nullptr, ctx, SEQ, DK, SEQ, SEQP, SEQP, EMB,
        (long)HEADS * SS, SS, (long)HEADS * DK * SEQP, (long)DK * SEQP,
        (long)SEQ * EMB, DK);

    // WO + bias + residual(x)
    tcgemm<128, true, false, true, false><<<dim3(EMB / 128, MT_, 1), 256, SM128>>>(
        ctx, woT, bo, x, x2, M, EMB, EMB, EMB, EMB, EMB, 0, 0, 0, 0, 0, 0);

    // LN2
    ln_kernel<<<M, 256>>>(x2, ln2_g, ln2_b, h2);

    // W1 + bias + GELU (+round)
    tcgemm<128, true, true, false, true><<<dim3(DFF / 128, MT_, 1), 256, SM128>>>(
        h2, w1T, bf1, nullptr, ff1, M, DFF, EMB, EMB, EMB, DFF, 0, 0, 0, 0, 0, 0);

    // W2 + bias + residual(x2) -> out
    tcgemm<128, true, false, true, false><<<dim3(EMB / 128, MT_, 1), 256, SM128>>>(
        ff1, w2T, bf2, x2, out, M, EMB, DFF, DFF, DFF, EMB, 0, 0, 0, 0, 0, 0);
}

// round 10
// speedup vs baseline: 3.9344x; 1.2259x over previous
// Transformer encoder block — Round 5: R4 flash attention with corrected tile loads.
// B=16, S=577, EMB=768, HEADS=12, DK=64, DFF=3072.

#include <cuda_runtime.h>
#include <cstdint>
#include <math.h>

#define EMB   768
#define HEADS 12
#define DK    64
#define DFF   3072
#define BATCH 16
#define SEQ   577
#define SEQP  600
#define NTOK  (BATCH * SEQ)           // 9232
#define NBH   (BATCH * HEADS)         // 192
#define QKVW  (3 * EMB)               // 2304
#define QB    128
#define KB    64
#define NKB   ((SEQ + KB - 1) / KB)   // 10

// ---------------- scratch (device globals) -----------------------------------
__device__ float g_h   [NTOK * EMB];
__device__ float g_qkv [(size_t)NTOK * QKVW];
__device__ float g_vT  [(size_t)NBH * DK * SEQP];
__device__ float g_ctx [NTOK * EMB];
__device__ float g_x2  [NTOK * EMB];
__device__ float g_h2  [NTOK * EMB];
__device__ float g_ff1 [(size_t)NTOK * DFF];
__device__ float g_wqkvT[QKVW * EMB];
__device__ float g_woT [EMB * EMB];
__device__ float g_w1T [DFF * EMB];
__device__ float g_w2T [EMB * DFF];
__device__ float g_bqkv[QKVW];

// ---------------- PTX helpers -------------------------------------------------
__device__ __forceinline__ uint32_t smem_u32(const void* p) {
    uint32_t a;
    asm("{ .reg .u64 t; cvta.to.shared.u64 t, %1; cvt.u32.u64 %0, t; }"
        : "=r"(a) : "l"(p));
    return a;
}
__device__ __forceinline__ float rnd_tf32(float x) {
    float r;
    asm("cvt.rna.tf32.f32 %0, %1;" : "=f"(r) : "f"(x));
    return r;
}
__device__ __forceinline__ void cp_async16(uint32_t dst, const void* src, int srcBytes) {
    asm volatile("cp.async.cg.shared.global [%0], [%1], 16, %2;"
                 :: "r"(dst), "l"(src), "r"(srcBytes) : "memory");
}
__device__ __forceinline__ void cp_commit() {
    asm volatile("cp.async.commit_group;" ::: "memory");
}
template <int N> __device__ __forceinline__ void cp_wait() {
    asm volatile("cp.async.wait_group %0;" :: "n"(N) : "memory");
}
__device__ __forceinline__ void mma_tf32(float* d, const uint32_t* a, const uint32_t* b) {
    asm volatile(
        "mma.sync.aligned.m16n8k8.row.col.f32.tf32.tf32.f32 "
        "{%0,%1,%2,%3}, {%4,%5,%6,%7}, {%8,%9}, {%0,%1,%2,%3};"
        : "+f"(d[0]), "+f"(d[1]), "+f"(d[2]), "+f"(d[3])
        : "r"(a[0]), "r"(a[1]), "r"(a[2]), "r"(a[3]), "r"(b[0]), "r"(b[1]));
}

// ---------------- generic tf32 mma.sync GEMM (dense projections) --------------
template <int BN, bool BIAS, bool GELU, bool RES, bool RND>
__global__ void __launch_bounds__(256) tcgemm(
    const float* __restrict__ A, const float* __restrict__ B,
    const float* __restrict__ bias, const float* __restrict__ res,
    float* __restrict__ C, int M, int N, int K,
    int lda, int ldb, int ldc)
{
    constexpr int WCOLS = 4;
    constexpr int WM = 64;
    constexpr int WN = BN / WCOLS;         // 32
    constexpr int MT = 4;
    constexpr int NT = WN / 8;             // 4
    constexpr int SA = 36;
    constexpr int ASTGF = 128 * SA;
    constexpr int BSTGF = BN * SA;
    constexpr int STGF  = ASTGF + BSTGF;

    extern __shared__ float smem[];
    const uint32_t sb = smem_u32(smem);
    const int tid = threadIdx.x;
    const int wid = tid >> 5, lane = tid & 31;
    const int g = lane >> 2, tig = lane & 3;
    const int wr = wid / WCOLS, wc = wid % WCOLS;
    const int wm0 = wr * WM, wn0 = wc * WN;

    const int m0 = blockIdx.y * 128, n0 = blockIdx.x * BN;
    const int nCh = (K + 31) >> 5;

    auto loadA = [&](int c, int buf) {
        uint32_t base = sb + (uint32_t)(buf * STGF) * 4u;
        int k0 = c << 5;
        #pragma unroll
        for (int i = 0; i < 4; i++) {
            int s = tid + i * 256, r = s >> 3, sg = s & 7;
            int gm = m0 + r, kb = k0 + sg * 4;
            int bytes = 0;
            if (gm < M) { int rem = (K - kb) * 4; bytes = rem >= 16 ? 16 : (rem > 0 ? rem : 0); }
            const float* src = A + (size_t)(gm < M ? gm : 0) * lda + (kb < K ? kb : 0);
            cp_async16(base + (uint32_t)(r * SA * 4 + sg * 16), src, bytes);
        }
    };
    auto loadB = [&](int c, int buf) {
        uint32_t base = sb + (uint32_t)(buf * STGF + ASTGF) * 4u;
        int k0 = c << 5;
        #pragma unroll
        for (int i = 0; i < BN / 32; i++) {
            int s = tid + i * 256, r = s >> 3, sg = s & 7;
            int gn = n0 + r, kb = k0 + sg * 4;
            int bytes = 0;
            if (gn < N) { int rem = (K - kb) * 4; bytes = rem >= 16 ? 16 : (rem > 0 ? rem : 0); }
            const float* src = B + (size_t)(gn < N ? gn : 0) * ldb + (kb < K ? kb : 0);
            cp_async16(base + (uint32_t)(r * SA * 4 + sg * 16), src, bytes);
        }
    };

    float acc[MT][NT][4];
    #pragma unroll
    for (int i = 0; i < MT; i++)
        #pragma unroll
        for (int j = 0; j < NT; j++)
            #pragma unroll
            for (int q = 0; q < 4; q++) acc[i][j][q] = 0.f;

    loadA(0, 0); loadB(0, 0); cp_commit();
    if (1 < nCh) { loadA(1, 1); loadB(1, 1); } cp_commit();

    for (int c = 0; c < nCh; c++) {
        int buf = c % 3;
        cp_wait<1>();
        __syncthreads();
        int p = c + 2;
        if (p < nCh) { loadA(p, p % 3); loadB(p, p % 3); }
        cp_commit();

        const float* Asf = smem + buf * STGF;
        const float* Bsf = Asf + ASTGF;
        #pragma unroll
        for (int ks = 0; ks < 4; ks++) {
            const int k = ks * 8;
            uint32_t af[MT][4], bf[NT][2];
            #pragma unroll
            for (int mt = 0; mt < MT; mt++) {
                const float* ap = Asf + (wm0 + mt * 16 + g) * SA + k + tig;
                af[mt][0] = __float_as_uint(ap[0]);
                af[mt][1] = __float_as_uint(ap[8 * SA]);
                af[mt][2] = __float_as_uint(ap[4]);
                af[mt][3] = __float_as_uint(ap[8 * SA + 4]);
            }
            #pragma unroll
            for (int nt = 0; nt < NT; nt++) {
                const float* bp = Bsf + (wn0 + nt * 8 + g) * SA + k + tig;
                bf[nt][0] = __float_as_uint(bp[0]);
                bf[nt][1] = __float_as_uint(bp[4]);
            }
            #pragma unroll
            for (int mt = 0; mt < MT; mt++)
                #pragma unroll
                for (int nt = 0; nt < NT; nt++)
                    mma_tf32(acc[mt][nt], af[mt], bf[nt]);
        }
    }

    #pragma unroll
    for (int mt = 0; mt < MT; mt++) {
        #pragma unroll
        for (int nt = 0; nt < NT; nt++) {
            int gm = m0 + wm0 + mt * 16 + g;
            int gn = n0 + wn0 + nt * 8 + 2 * tig;
            #pragma unroll
            for (int half = 0; half < 2; half++) {
                int gmr = gm + half * 8;
                if (gmr >= M) continue;
                float v0 = acc[mt][nt][half * 2 + 0];
                float v1 = acc[mt][nt][half * 2 + 1];
                if (BIAS) { v0 += bias[gn]; v1 += bias[gn + 1]; }
                if (GELU) {
                    v0 = 0.5f * v0 * (1.0f + erff(v0 * 0.7071067811865475f));
                    v1 = 0.5f * v1 * (1.0f + erff(v1 * 0.7071067811865475f));
                }
                float* crow = C + (size_t)gmr * ldc;
                if (RES) {
                    const float* rrow = res + (size_t)gmr * ldc;
                    v0 += rrow[gn]; v1 += rrow[gn + 1];
                }
                if (RND) { v0 = rnd_tf32(v0); v1 = rnd_tf32(v1); }
                *reinterpret_cast<float2*>(crow + gn) = make_float2(v0, v1);
            }
        }
    }
}

// ---------------- fused flash attention ---------------------------------------
// grid (5, NBH); 256 thr (8 warps); warp w owns Q rows 16w..16w+15.
// smem: Qs[128][68] (reused as Ps), Ks[2][64][68], Vs[2][64][68].
__global__ void __launch_bounds__(256) flash_kernel(
    const float* __restrict__ qkv, const float* __restrict__ vT,
    float* __restrict__ ctx)
{
    constexpr int ST = 68;
    extern __shared__ float fsm[];
    float* Qs = fsm;
    float* Ks = fsm + 128 * ST;
    float* Vs = Ks + 2 * 64 * ST;
    const uint32_t sb = smem_u32(fsm);
    const uint32_t ks_off = 128 * ST * 4u;
    const uint32_t vs_off = ks_off + 2 * 64 * ST * 4u;

    const int tid = threadIdx.x, wid = tid >> 5, lane = tid & 31;
    const int g = lane >> 2, tig = lane & 3;
    const int wm0 = wid * 16;
    const int z = blockIdx.y, b = z / HEADS, h = z % HEADS;
    const int m0 = blockIdx.x * QB;

    const float* Qg = qkv + (size_t)b * SEQ * QKVW + h * DK;
    const float* Kg = qkv + (size_t)b * SEQ * QKVW + EMB + h * DK;
    const float* Vg = vT + (size_t)z * DK * SEQP;

    // Q tile load: 128 rows x 64 floats = 2048 x 16B chunks (8 x 256 threads)
    #pragma unroll
    for (int i = 0; i < 8; i++) {
        int s = tid + i * 256, r = s >> 4, sg = s & 15;
        int gm = m0 + r;
        int bytes = (gm < SEQ) ? 16 : 0;
        cp_async16(sb + (uint32_t)(r * ST + sg * 4) * 4u,
                   Qg + (size_t)(gm < SEQ ? gm : 0) * QKVW + sg * 4, bytes);
    }
    cp_commit();

    auto loadKV = [&](int j, int buf) {
        int k0 = j * KB;
        // K: 64 rows (key) x 64 floats (dk) = 1024 chunks
        #pragma unroll
        for (int i = 0; i < 4; i++) {
            int s = tid + i * 256, r = s >> 4, sg = s & 15;
            int gs = k0 + r;
            int bytes = (gs < SEQ) ? 16 : 0;
            cp_async16(sb + ks_off + (uint32_t)(buf * 64 * ST + r * ST + sg * 4) * 4u,
                       Kg + (size_t)(gs < SEQ ? gs : 0) * QKVW + sg * 4, bytes);
        }
        // V: 64 rows (dk) x 64 floats (key chunk) = 1024 chunks; clamp to row end
        #pragma unroll
        for (int i = 0; i < 4; i++) {
            int s = tid + i * 256, r = s >> 4, sg = s & 15;
            int col = k0 + sg * 4;
            int bytes = (col + 4 <= SEQP) ? 16 : 0;
            cp_async16(sb + vs_off + (uint32_t)(buf * 64 * ST + r * ST + sg * 4) * 4u,
                       Vg + (size_t)r * SEQP + (bytes ? col : 0), bytes);
        }
    };
    loadKV(0, 0);
    cp_commit();

    // wait for Q (leave KV0 in flight), extract Q fragments to registers
    cp_wait<1>();
    __syncthreads();
    uint32_t qf[8][4];
    #pragma unroll
    for (int ks = 0; ks < 8; ks++) {
        const float* ap = Qs + (wm0 + g) * ST + ks * 8 + tig;
        qf[ks][0] = __float_as_uint(ap[0]);
        qf[ks][1] = __float_as_uint(ap[8 * ST]);
        qf[ks][2] = __float_as_uint(ap[4]);
        qf[ks][3] = __float_as_uint(ap[8 * ST + 4]);
    }

    float m_r0 = -1e30f, m_r1 = -1e30f, l_r0 = 0.f, l_r1 = 0.f;
    float acc_o[8][4];
    #pragma unroll
    for (int nt = 0; nt < 8; nt++)
        #pragma unroll
        for (int q = 0; q < 4; q++) acc_o[nt][q] = 0.f;

    for (int j = 0; j < NKB; j++) {
        const int buf = j & 1;
        cp_wait<0>();
        __syncthreads();
        if (j + 1 < NKB) loadKV(j + 1, buf ^ 1);
        cp_commit();

        const float* Kb = Ks + buf * 64 * ST;
        const float* Vb = Vs + buf * 64 * ST;

        // S = Q @ K^T  (warp: 16 x 64)
        float s_acc[8][4];
        #pragma unroll
        for (int nt = 0; nt < 8; nt++)
            #pragma unroll
            for (int q = 0; q < 4; q++) s_acc[nt][q] = 0.f;
        #pragma unroll
        for (int ks = 0; ks < 8; ks++) {
            const int k = ks * 8;
            uint32_t bf[8][2];
            #pragma unroll
            for (int nt = 0; nt < 8; nt++) {
                const float* bp = Kb + (nt * 8 + g) * ST + k + tig;
                bf[nt][0] = __float_as_uint(bp[0]);
                bf[nt][1] = __float_as_uint(bp[4]);
            }
            #pragma unroll
            for (int nt = 0; nt < 8; nt++)
                mma_tf32(s_acc[nt], qf[ks], bf[nt]);
        }

        // mask + row max
        const int colbase = j * KB;
        float mx0 = -1e30f, mx1 = -1e30f;
        #pragma unroll
        for (int nt = 0; nt < 8; nt++) {
            int c0 = colbase + nt * 8 + 2 * tig;
            if (c0 >= SEQ)     { s_acc[nt][0] = -1e30f; s_acc[nt][2] = -1e30f; }
            if (c0 + 1 >= SEQ) { s_acc[nt][1] = -1e30f; s_acc[nt][3] = -1e30f; }
            mx0 = fmaxf(mx0, fmaxf(s_acc[nt][0], s_acc[nt][1]));
            mx1 = fmaxf(mx1, fmaxf(s_acc[nt][2], s_acc[nt][3]));
        }
        mx0 = fmaxf(mx0, __shfl_xor_sync(0xffffffffu, mx0, 1));
        mx0 = fmaxf(mx0, __shfl_xor_sync(0xffffffffu, mx0, 2));
        mx1 = fmaxf(mx1, __shfl_xor_sync(0xffffffffu, mx1, 1));
        mx1 = fmaxf(mx1, __shfl_xor_sync(0xffffffffu, mx1, 2));

        float mn0 = fmaxf(m_r0, mx0), mn1 = fmaxf(m_r1, mx1);
        float al0 = __expf(m_r0 - mn0), al1 = __expf(m_r1 - mn1);
        m_r0 = mn0; m_r1 = mn1;

        // p = exp(S - m), row sums
        float sum0 = 0.f, sum1 = 0.f;
        #pragma unroll
        for (int nt = 0; nt < 8; nt++) {
            s_acc[nt][0] = __expf(s_acc[nt][0] - mn0);
            s_acc[nt][1] = __expf(s_acc[nt][1] - mn0);
            s_acc[nt][2] = __expf(s_acc[nt][2] - mn1);
            s_acc[nt][3] = __expf(s_acc[nt][3] - mn1);
            sum0 += s_acc[nt][0] + s_acc[nt][1];
            sum1 += s_acc[nt][2] + s_acc[nt][3];
        }
        sum0 += __shfl_xor_sync(0xffffffffu, sum0, 1);
        sum0 += __shfl_xor_sync(0xffffffffu, sum0, 2);
        sum1 += __shfl_xor_sync(0xffffffffu, sum1, 1);
        sum1 += __shfl_xor_sync(0xffffffffu, sum1, 2);
        l_r0 = l_r0 * al0 + sum0;
        l_r1 = l_r1 * al1 + sum1;

        // rescale O
        #pragma unroll
        for (int nt = 0; nt < 8; nt++) {
            acc_o[nt][0] *= al0; acc_o[nt][1] *= al0;
            acc_o[nt][2] *= al1; acc_o[nt][3] *= al1;
        }

        // P -> smem (own rows only), then O += P @ V
        #pragma unroll
        for (int nt = 0; nt < 8; nt++) {
            int col = nt * 8 + 2 * tig;
            *reinterpret_cast<float2*>(Qs + (wm0 + g) * ST + col) =
                make_float2(rnd_tf32(s_acc[nt][0]), rnd_tf32(s_acc[nt][1]));
            *reinterpret_cast<float2*>(Qs + (wm0 + g + 8) * ST + col) =
                make_float2(rnd_tf32(s_acc[nt][2]), rnd_tf32(s_acc[nt][3]));
        }
        __syncwarp();

        #pragma unroll
        for (int ks = 0; ks < 8; ks++) {
            const int k = ks * 8;
            uint32_t af[4], bf[8][2];
            const float* ap = Qs + (wm0 + g) * ST + k + tig;
            af[0] = __float_as_uint(ap[0]);
            af[1] = __float_as_uint(ap[8 * ST]);
            af[2] = __float_as_uint(ap[4]);
            af[3] = __float_as_uint(ap[8 * ST + 4]);
            #pragma unroll
            for (int nt = 0; nt < 8; nt++) {
                const float* bp = Vb + (nt * 8 + g) * ST + k + tig;
                bf[nt][0] = __float_as_uint(bp[0]);
                bf[nt][1] = __float_as_uint(bp[4]);
            }
            #pragma unroll
            for (int nt = 0; nt < 8; nt++)
                mma_tf32(acc_o[nt], af, bf[nt]);
        }
        __syncwarp();
    }

    // final: normalize, round, store to ctx
    float inv0 = 1.0f / l_r0, inv1 = 1.0f / l_r1;
    int r0 = m0 + wm0 + g, r1 = r0 + 8;
    float* c0 = ctx + ((size_t)b * SEQ + r0) * EMB + h * DK;
    float* c1 = ctx + ((size_t)b * SEQ + r1) * EMB + h * DK;
    #pragma unroll
    for (int nt = 0; nt < 8; nt++) {
        int col = nt * 8 + 2 * tig;
        if (r0 < SEQ)
            *reinterpret_cast<float2*>(c0 + col) =
                make_float2(rnd_tf32(acc_o[nt][0] * inv0), rnd_tf32(acc_o[nt][1] * inv0));
        if (r1 < SEQ)
            *reinterpret_cast<float2*>(c1 + col) =
                make_float2(rnd_tf32(acc_o[nt][2] * inv1), rnd_tf32(acc_o[nt][3] * inv1));
    }
}

// ---------------- LayerNorm (tf32-rounded output) -----------------------------
__global__ void __launch_bounds__(256) ln_kernel(
    const float* __restrict__ x, const float* __restrict__ g,
    const float* __restrict__ b, float* __restrict__ out)
{
    int row = blockIdx.x;
    const float* xr = x + (size_t)row * EMB;
    float* orow = out + (size_t)row * EMB;
    int tid = threadIdx.x;

    float v0 = xr[tid], v1 = xr[tid + 256], v2 = xr[tid + 512];
    float s = v0 + v1 + v2;
    __shared__ float red[8];
    #pragma unroll
    for (int o = 16; o; o >>= 1) s += __shfl_xor_sync(0xffffffffu, s, o);
    if ((tid & 31) == 0) red[tid >> 5] = s;
    __syncthreads();
    float tot = 0.f;
    #pragma unroll
    for (int i = 0; i < 8; i++) tot += red[i];
    float mu = tot * (1.0f / EMB);
    __syncthreads();
    float d0 = v0 - mu, d1 = v1 - mu, d2 = v2 - mu;
    float qv = d0 * d0 + d1 * d1 + d2 * d2;
    #pragma unroll
    for (int o = 16; o; o >>= 1) qv += __shfl_xor_sync(0xffffffffu, qv, o);
    if ((tid & 31) == 0) red[tid >> 5] = qv;
    __syncthreads();
    float tot2 = 0.f;
    #pragma unroll
    for (int i = 0; i < 8; i++) tot2 += red[i];
    float rstd = rsqrtf(tot2 * (1.0f / EMB) + 1e-5f);

    orow[tid]       = rnd_tf32(d0 * rstd * g[tid]       + b[tid]);
    orow[tid + 256] = rnd_tf32(d1 * rstd * g[tid + 256] + b[tid + 256]);
    orow[tid + 512] = rnd_tf32(d2 * rstd * g[tid + 512] + b[tid + 512]);
}

// ---------------- weight transpose + tf32 round -------------------------------
__global__ void __launch_bounds__(256) transpose_rnd(
    const float* __restrict__ in, float* __restrict__ out, int K, int N)
{
    __shared__ float t[32][33];
    int bx = blockIdx.x * 32;
    int by = blockIdx.y * 32;
    int tx = threadIdx.x & 31, ty = threadIdx.x >> 5;
    #pragma unroll
    for (int i = 0; i < 32; i += 8)
        t[ty + i][tx] = in[(size_t)(by + ty + i) * N + bx + tx];
    __syncthreads();
    #pragma unroll
    for (int i = 0; i < 32; i += 8)
        out[(size_t)(bx + ty + i) * K + by + tx] = rnd_tf32(t[tx][ty + i]);
}

// ---------------- v head transpose --------------------------------------------
__global__ void __launch_bounds__(256) vtrans_kernel(
    const float* __restrict__ qkv, float* __restrict__ vT)
{
    int z = blockIdx.z, b = z / HEADS, h = z % HEADS;
    int s0 = blockIdx.x * 32, d0 = blockIdx.y * 32;
    __shared__ float t[32][33];
    int tx = threadIdx.x & 31, ty = threadIdx.x >> 5;
    const float* src = qkv + (size_t)b * SEQ * QKVW + 2 * EMB + h * DK;
    #pragma unroll
    for (int i = 0; i < 32; i += 8) {
        int s = s0 + ty + i;
        t[ty + i][tx] = (s < SEQ) ? src[(size_t)s * QKVW + d0 + tx] : 0.f;
    }
    __syncthreads();
    float* dst = vT + ((size_t)z * DK + d0) * SEQP + s0;
    #pragma unroll
    for (int i = 0; i < 32; i += 8) {
        if (s0 + tx < SEQ) dst[(size_t)(ty + i) * SEQP + tx] = t[tx][ty + i];
    }
}

__global__ void concat_bias(const float* __restrict__ bq, const float* __restrict__ bk,
                            const float* __restrict__ bv, float* __restrict__ o)
{
    int i = blockIdx.x * 256 + threadIdx.x;
    if (i < EMB) { o[i] = bq[i]; o[i + EMB] = bk[i]; o[i + 2 * EMB] = bv[i]; }
}

// ---------------- host orchestration ------------------------------------------
extern "C" void kernel_launch(void* const* d_in, const int* in_sizes, int n_in,
                              void* d_out, int out_size)
{
    const float* x     = (const float*)d_in[0];
    const float* wq    = (const float*)d_in[1];
    const float* bq    = (const float*)d_in[2];
    const float* wk    = (const float*)d_in[3];
    const float* bk    = (const float*)d_in[4];
    const float* wv    = (const float*)d_in[5];
    const float* bv    = (const float*)d_in[6];
    const float* wo    = (const float*)d_in[7];
    const float* bo    = (const float*)d_in[8];
    const float* w1    = (const float*)d_in[9];
    const float* bf1   = (const float*)d_in[10];
    const float* w2    = (const float*)d_in[11];
    const float* bf2   = (const float*)d_in[12];
    const float* ln1_g = (const float*)d_in[13];
    const float* ln1_b = (const float*)d_in[14];
    const float* ln2_g = (const float*)d_in[15];
    const float* ln2_b = (const float*)d_in[16];
    float* out = (float*)d_out;

    float *h, *qkv, *vT, *ctx, *x2, *h2, *ff1;
    float *wqkvT, *woT, *w1T, *w2T, *bqkv;
    cudaGetSymbolAddress((void**)&h,     g_h);
    cudaGetSymbolAddress((void**)&qkv,   g_qkv);
    cudaGetSymbolAddress((void**)&vT,    g_vT);
    cudaGetSymbolAddress((void**)&ctx,   g_ctx);
    cudaGetSymbolAddress((void**)&x2,    g_x2);
    cudaGetSymbolAddress((void**)&h2,    g_h2);
    cudaGetSymbolAddress((void**)&ff1,   g_ff1);
    cudaGetSymbolAddress((void**)&wqkvT, g_wqkvT);
    cudaGetSymbolAddress((void**)&woT,   g_woT);
    cudaGetSymbolAddress((void**)&w1T,   g_w1T);
    cudaGetSymbolAddress((void**)&w2T,   g_w2T);
    cudaGetSymbolAddress((void**)&bqkv,  g_bqkv);

    const int SM128 = 3 * (128 + 128) * 36 * 4;          // 110592
    const int SMFL  = (128 * 68 + 4 * 64 * 68) * 4;      // 104448
    cudaFuncSetAttribute(tcgemm<128, true,  false, false, true >, cudaFuncAttributeMaxDynamicSharedMemorySize, SM128);
    cudaFuncSetAttribute(tcgemm<128, true,  false, true,  false>, cudaFuncAttributeMaxDynamicSharedMemorySize, SM128);
    cudaFuncSetAttribute(tcgemm<128, true,  true,  false, true >, cudaFuncAttributeMaxDynamicSharedMemorySize, SM128);
    cudaFuncSetAttribute(flash_kernel, cudaFuncAttributeMaxDynamicSharedMemorySize, SMFL);

    const int M = NTOK;
    const int MT_ = (M + 127) / 128;       // 73
    const int ST_ = (SEQ + 127) / 128;     // 5

    // weight prep
    transpose_rnd<<<dim3(EMB / 32, EMB / 32), 256>>>(wq, wqkvT,                 EMB, EMB);
    transpose_rnd<<<dim3(EMB / 32, EMB / 32), 256>>>(wk, wqkvT + EMB * EMB,     EMB, EMB);
    transpose_rnd<<<dim3(EMB / 32, EMB / 32), 256>>>(wv, wqkvT + 2 * EMB * EMB, EMB, EMB);
    transpose_rnd<<<dim3(EMB / 32, EMB / 32), 256>>>(wo, woT, EMB, EMB);
    transpose_rnd<<<dim3(DFF / 32, EMB / 32), 256>>>(w1, w1T, EMB, DFF);
    transpose_rnd<<<dim3(EMB / 32, DFF / 32), 256>>>(w2, w2T, DFF, EMB);
    concat_bias<<<3, 256>>>(bq, bk, bv, bqkv);

    // LN1
    ln_kernel<<<M, 256>>>(x, ln1_g, ln1_b, h);

    // fused QKV
    tcgemm<128, true, false, false, true><<<dim3(QKVW / 128, MT_, 1), 256, SM128>>>(
        h, wqkvT, bqkv, nullptr, qkv, M, QKVW, EMB, EMB, EMB, QKVW);

    // v transpose per head
    vtrans_kernel<<<dim3((SEQ + 31) / 32, DK / 32, NBH), 256>>>(qkv, vT);

    // fused attention (scores + softmax + ctx)
    flash_kernel<<<dim3(ST_, NBH), 256, SMFL>>>(qkv, vT, ctx);

    // WO + bias + residual(x)
    tcgemm<128, true, false, true, false><<<dim3(EMB / 128, MT_, 1), 256, SM128>>>(
        ctx, woT, bo, x, x2, M, EMB, EMB, EMB, EMB, EMB);

    // LN2
    ln_kernel<<<M, 256>>>(x2, ln2_g, ln2_b, h2);

    // W1 + bias + GELU
    tcgemm<128, true, true, false, true><<<dim3(DFF / 128, MT_, 1), 256, SM128>>>(
        h2, w1T, bf1, nullptr, ff1, M, DFF, EMB, EMB, EMB, DFF);

    // W2 + bias + residual(x2) -> out
    tcgemm<128, true, false, true, false><<<dim3(EMB / 128, MT_, 1), 256, SM128>>>(
        ff1, w2T, bf2, x2, out, M, EMB, DFF, DFF, DFF, EMB);
}

// round 11
// speedup vs baseline: 4.1680x; 1.0594x over previous
// Transformer encoder block — Round 6: 2-stage tcgemm pipeline, 2 blocks/SM.
// B=16, S=577, EMB=768, HEADS=12, DK=64, DFF=3072.

#include <cuda_runtime.h>
#include <cstdint>
#include <math.h>

#define EMB   768
#define HEADS 12
#define DK    64
#define DFF   3072
#define BATCH 16
#define SEQ   577
#define SEQP  600
#define NTOK  (BATCH * SEQ)           // 9232
#define NBH   (BATCH * HEADS)         // 192
#define QKVW  (3 * EMB)               // 2304
#define QB    128
#define KB    64
#define NKB   ((SEQ + KB - 1) / KB)   // 10

// ---------------- scratch (device globals) -----------------------------------
__device__ float g_h   [NTOK * EMB];
__device__ float g_qkv [(size_t)NTOK * QKVW];
__device__ float g_vT  [(size_t)NBH * DK * SEQP];
__device__ float g_ctx [NTOK * EMB];
__device__ float g_x2  [NTOK * EMB];
__device__ float g_h2  [NTOK * EMB];
__device__ float g_ff1 [(size_t)NTOK * DFF];
__device__ float g_wqkvT[QKVW * EMB];
__device__ float g_woT [EMB * EMB];
__device__ float g_w1T [DFF * EMB];
__device__ float g_w2T [EMB * DFF];
__device__ float g_bqkv[QKVW];

// ---------------- PTX helpers -------------------------------------------------
__device__ __forceinline__ uint32_t smem_u32(const void* p) {
    uint32_t a;
    asm("{ .reg .u64 t; cvta.to.shared.u64 t, %1; cvt.u32.u64 %0, t; }"
        : "=r"(a) : "l"(p));
    return a;
}
__device__ __forceinline__ float rnd_tf32(float x) {
    float r;
    asm("cvt.rna.tf32.f32 %0, %1;" : "=f"(r) : "f"(x));
    return r;
}
__device__ __forceinline__ void cp_async16(uint32_t dst, const void* src, int srcBytes) {
    asm volatile("cp.async.cg.shared.global [%0], [%1], 16, %2;"
                 :: "r"(dst), "l"(src), "r"(srcBytes) : "memory");
}
__device__ __forceinline__ void cp_commit() {
    asm volatile("cp.async.commit_group;" ::: "memory");
}
template <int N> __device__ __forceinline__ void cp_wait() {
    asm volatile("cp.async.wait_group %0;" :: "n"(N) : "memory");
}
__device__ __forceinline__ void mma_tf32(float* d, const uint32_t* a, const uint32_t* b) {
    asm volatile(
        "mma.sync.aligned.m16n8k8.row.col.f32.tf32.tf32.f32 "
        "{%0,%1,%2,%3}, {%4,%5,%6,%7}, {%8,%9}, {%0,%1,%2,%3};"
        : "+f"(d[0]), "+f"(d[1]), "+f"(d[2]), "+f"(d[3])
        : "r"(a[0]), "r"(a[1]), "r"(a[2]), "r"(a[3]), "r"(b[0]), "r"(b[1]));
}

// ---------------- generic tf32 mma.sync GEMM (dense projections) --------------
// 2-stage cp.async pipeline, 2 blocks/SM (launch_bounds minBlocks=2).
template <int BN, bool BIAS, bool GELU, bool RES, bool RND>
__global__ void __launch_bounds__(256, 2) tcgemm(
    const float* __restrict__ A, const float* __restrict__ B,
    const float* __restrict__ bias, const float* __restrict__ res,
    float* __restrict__ C, int M, int N, int K,
    int lda, int ldb, int ldc)
{
    constexpr int WCOLS = 4;
    constexpr int WM = 64;
    constexpr int WN = BN / WCOLS;         // 32
    constexpr int MT = 4;
    constexpr int NT = WN / 8;             // 4
    constexpr int SA = 36;
    constexpr int ASTGF = 128 * SA;
    constexpr int BSTGF = BN * SA;
    constexpr int STGF  = ASTGF + BSTGF;

    extern __shared__ float smem[];
    const uint32_t sb = smem_u32(smem);
    const int tid = threadIdx.x;
    const int wid = tid >> 5, lane = tid & 31;
    const int g = lane >> 2, tig = lane & 3;
    const int wr = wid / WCOLS, wc = wid % WCOLS;
    const int wm0 = wr * WM, wn0 = wc * WN;

    const int m0 = blockIdx.y * 128, n0 = blockIdx.x * BN;
    const int nCh = (K + 31) >> 5;

    auto loadA = [&](int c, int buf) {
        uint32_t base = sb + (uint32_t)(buf * STGF) * 4u;
        int k0 = c << 5;
        #pragma unroll
        for (int i = 0; i < 4; i++) {
            int s = tid + i * 256, r = s >> 3, sg = s & 7;
            int gm = m0 + r, kb = k0 + sg * 4;
            int bytes = 0;
            if (gm < M) { int rem = (K - kb) * 4; bytes = rem >= 16 ? 16 : (rem > 0 ? rem : 0); }
            const float* src = A + (size_t)(gm < M ? gm : 0) * lda + (kb < K ? kb : 0);
            cp_async16(base + (uint32_t)(r * SA * 4 + sg * 16), src, bytes);
        }
    };
    auto loadB = [&](int c, int buf) {
        uint32_t base = sb + (uint32_t)(buf * STGF + ASTGF) * 4u;
        int k0 = c << 5;
        #pragma unroll
        for (int i = 0; i < BN / 32; i++) {
            int s = tid + i * 256, r = s >> 3, sg = s & 7;
            int gn = n0 + r, kb = k0 + sg * 4;
            int bytes = 0;
            if (gn < N) { int rem = (K - kb) * 4; bytes = rem >= 16 ? 16 : (rem > 0 ? rem : 0); }
            const float* src = B + (size_t)(gn < N ? gn : 0) * ldb + (kb < K ? kb : 0);
            cp_async16(base + (uint32_t)(r * SA * 4 + sg * 16), src, bytes);
        }
    };

    float acc[MT][NT][4];
    #pragma unroll
    for (int i = 0; i < MT; i++)
        #pragma unroll
        for (int j = 0; j < NT; j++)
            #pragma unroll
            for (int q = 0; q < 4; q++) acc[i][j][q] = 0.f;

    loadA(0, 0); loadB(0, 0); cp_commit();

    for (int c = 0; c < nCh; c++) {
        const int buf = c & 1;
        if (c + 1 < nCh) { loadA(c + 1, buf ^ 1); loadB(c + 1, buf ^ 1); }
        cp_commit();                       // group every iter (may be empty)
        cp_wait<1>();                      // chunk c resident; c+1 in flight
        __syncthreads();

        const float* Asf = smem + buf * STGF;
        const float* Bsf = Asf + ASTGF;
        #pragma unroll
        for (int ks = 0; ks < 4; ks++) {
            const int k = ks * 8;
            uint32_t af[MT][4], bf[NT][2];
            #pragma unroll
            for (int mt = 0; mt < MT; mt++) {
                const float* ap = Asf + (wm0 + mt * 16 + g) * SA + k + tig;
                af[mt][0] = __float_as_uint(ap[0]);
                af[mt][1] = __float_as_uint(ap[8 * SA]);
                af[mt][2] = __float_as_uint(ap[4]);
                af[mt][3] = __float_as_uint(ap[8 * SA + 4]);
            }
            #pragma unroll
            for (int nt = 0; nt < NT; nt++) {
                const float* bp = Bsf + (wn0 + nt * 8 + g) * SA + k + tig;
                bf[nt][0] = __float_as_uint(bp[0]);
                bf[nt][1] = __float_as_uint(bp[4]);
            }
            #pragma unroll
            for (int mt = 0; mt < MT; mt++)
                #pragma unroll
                for (int nt = 0; nt < NT; nt++)
                    mma_tf32(acc[mt][nt], af[mt], bf[nt]);
        }
        __syncthreads();                   // protect buf^1 before next-iter load
    }

    #pragma unroll
    for (int mt = 0; mt < MT; mt++) {
        #pragma unroll
        for (int nt = 0; nt < NT; nt++) {
            int gm = m0 + wm0 + mt * 16 + g;
            int gn = n0 + wn0 + nt * 8 + 2 * tig;
            #pragma unroll
            for (int half = 0; half < 2; half++) {
                int gmr = gm + half * 8;
                if (gmr >= M) continue;
                float v0 = acc[mt][nt][half * 2 + 0];
                float v1 = acc[mt][nt][half * 2 + 1];
                if (BIAS) { v0 += bias[gn]; v1 += bias[gn + 1]; }
                if (GELU) {
                    v0 = 0.5f * v0 * (1.0f + erff(v0 * 0.7071067811865475f));
                    v1 = 0.5f * v1 * (1.0f + erff(v1 * 0.7071067811865475f));
                }
                float* crow = C + (size_t)gmr * ldc;
                if (RES) {
                    const float* rrow = res + (size_t)gmr * ldc;
                    v0 += rrow[gn]; v1 += rrow[gn + 1];
                }
                if (RND) { v0 = rnd_tf32(v0); v1 = rnd_tf32(v1); }
                *reinterpret_cast<float2*>(crow + gn) = make_float2(v0, v1);
            }
        }
    }
}

// ---------------- fused flash attention (unchanged from R5) -------------------
__global__ void __launch_bounds__(256) flash_kernel(
    const float* __restrict__ qkv, const float* __restrict__ vT,
    float* __restrict__ ctx)
{
    constexpr int ST = 68;
    extern __shared__ float fsm[];
    float* Qs = fsm;
    float* Ks = fsm + 128 * ST;
    float* Vs = Ks + 2 * 64 * ST;
    const uint32_t sb = smem_u32(fsm);
    const uint32_t ks_off = 128 * ST * 4u;
    const uint32_t vs_off = ks_off + 2 * 64 * ST * 4u;

    const int tid = threadIdx.x, wid = tid >> 5, lane = tid & 31;
    const int g = lane >> 2, tig = lane & 3;
    const int wm0 = wid * 16;
    const int z = blockIdx.y, b = z / HEADS, h = z % HEADS;
    const int m0 = blockIdx.x * QB;

    const float* Qg = qkv + (size_t)b * SEQ * QKVW + h * DK;
    const float* Kg = qkv + (size_t)b * SEQ * QKVW + EMB + h * DK;
    const float* Vg = vT + (size_t)z * DK * SEQP;

    #pragma unroll
    for (int i = 0; i < 8; i++) {
        int s = tid + i * 256, r = s >> 4, sg = s & 15;
        int gm = m0 + r;
        int bytes = (gm < SEQ) ? 16 : 0;
        cp_async16(sb + (uint32_t)(r * ST + sg * 4) * 4u,
                   Qg + (size_t)(gm < SEQ ? gm : 0) * QKVW + sg * 4, bytes);
    }
    cp_commit();

    auto loadKV = [&](int j, int buf) {
        int k0 = j * KB;
        #pragma unroll
        for (int i = 0; i < 4; i++) {
            int s = tid + i * 256, r = s >> 4, sg = s & 15;
            int gs = k0 + r;
            int bytes = (gs < SEQ) ? 16 : 0;
            cp_async16(sb + ks_off + (uint32_t)(buf * 64 * ST + r * ST + sg * 4) * 4u,
                       Kg + (size_t)(gs < SEQ ? gs : 0) * QKVW + sg * 4, bytes);
        }
        #pragma unroll
        for (int i = 0; i < 4; i++) {
            int s = tid + i * 256, r = s >> 4, sg = s & 15;
            int col = k0 + sg * 4;
            int bytes = (col + 4 <= SEQP) ? 16 : 0;
            cp_async16(sb + vs_off + (uint32_t)(buf * 64 * ST + r * ST + sg * 4) * 4u,
                       Vg + (size_t)r * SEQP + (bytes ? col : 0), bytes);
        }
    };
    loadKV(0, 0);
    cp_commit();

    cp_wait<1>();
    __syncthreads();
    uint32_t qf[8][4];
    #pragma unroll
    for (int ks = 0; ks < 8; ks++) {
        const float* ap = Qs + (wm0 + g) * ST + ks * 8 + tig;
        qf[ks][0] = __float_as_uint(ap[0]);
        qf[ks][1] = __float_as_uint(ap[8 * ST]);
        qf[ks][2] = __float_as_uint(ap[4]);
        qf[ks][3] = __float_as_uint(ap[8 * ST + 4]);
    }

    float m_r0 = -1e30f, m_r1 = -1e30f, l_r0 = 0.f, l_r1 = 0.f;
    float acc_o[8][4];
    #pragma unroll
    for (int nt = 0; nt < 8; nt++)
        #pragma unroll
        for (int q = 0; q < 4; q++) acc_o[nt][q] = 0.f;

    for (int j = 0; j < NKB; j++) {
        const int buf = j & 1;
        cp_wait<0>();
        __syncthreads();
        if (j + 1 < NKB) loadKV(j + 1, buf ^ 1);
        cp_commit();

        const float* Kb = Ks + buf * 64 * ST;
        const float* Vb = Vs + buf * 64 * ST;

        float s_acc[8][4];
        #pragma unroll
        for (int nt = 0; nt < 8; nt++)
            #pragma unroll
            for (int q = 0; q < 4; q++) s_acc[nt][q] = 0.f;
        #pragma unroll
        for (int ks = 0; ks < 8; ks++) {
            const int k = ks * 8;
            uint32_t bf[8][2];
            #pragma unroll
            for (int nt = 0; nt < 8; nt++) {
                const float* bp = Kb + (nt * 8 + g) * ST + k + tig;
                bf[nt][0] = __float_as_uint(bp[0]);
                bf[nt][1] = __float_as_uint(bp[4]);
            }
            #pragma unroll
            for (int nt = 0; nt < 8; nt++)
                mma_tf32(s_acc[nt], qf[ks], bf[nt]);
        }

        const int colbase = j * KB;
        float mx0 = -1e30f, mx1 = -1e30f;
        #pragma unroll
        for (int nt = 0; nt < 8; nt++) {
            int c0 = colbase + nt * 8 + 2 * tig;
            if (c0 >= SEQ)     { s_acc[nt][0] = -1e30f; s_acc[nt][2] = -1e30f; }
            if (c0 + 1 >= SEQ) { s_acc[nt][1] = -1e30f; s_acc[nt][3] = -1e30f; }
            mx0 = fmaxf(mx0, fmaxf(s_acc[nt][0], s_acc[nt][1]));
            mx1 = fmaxf(mx1, fmaxf(s_acc[nt][2], s_acc[nt][3]));
        }
        mx0 = fmaxf(mx0, __shfl_xor_sync(0xffffffffu, mx0, 1));
        mx0 = fmaxf(mx0, __shfl_xor_sync(0xffffffffu, mx0, 2));
        mx1 = fmaxf(mx1, __shfl_xor_sync(0xffffffffu, mx1, 1));
        mx1 = fmaxf(mx1, __shfl_xor_sync(0xffffffffu, mx1, 2));

        float mn0 = fmaxf(m_r0, mx0), mn1 = fmaxf(m_r1, mx1);
        float al0 = __expf(m_r0 - mn0), al1 = __expf(m_r1 - mn1);
        m_r0 = mn0; m_r1 = mn1;

        float sum0 = 0.f, sum1 = 0.f;
        #pragma unroll
        for (int nt = 0; nt < 8; nt++) {
            s_acc[nt][0] = __expf(s_acc[nt][0] - mn0);
            s_acc[nt][1] = __expf(s_acc[nt][1] - mn0);
            s_acc[nt][2] = __expf(s_acc[nt][2] - mn1);
            s_acc[nt][3] = __expf(s_acc[nt][3] - mn1);
            sum0 += s_acc[nt][0] + s_acc[nt][1];
            sum1 += s_acc[nt][2] + s_acc[nt][3];
        }
        sum0 += __shfl_xor_sync(0xffffffffu, sum0, 1);
        sum0 += __shfl_xor_sync(0xffffffffu, sum0, 2);
        sum1 += __shfl_xor_sync(0xffffffffu, sum1, 1);
        sum1 += __shfl_xor_sync(0xffffffffu, sum1, 2);
        l_r0 = l_r0 * al0 + sum0;
        l_r1 = l_r1 * al1 + sum1;

        #pragma unroll
        for (int nt = 0; nt < 8; nt++) {
            acc_o[nt][0] *= al0; acc_o[nt][1] *= al0;
            acc_o[nt][2] *= al1; acc_o[nt][3] *= al1;
        }

        #pragma unroll
        for (int nt = 0; nt < 8; nt++) {
            int col = nt * 8 + 2 * tig;
            *reinterpret_cast<float2*>(Qs + (wm0 + g) * ST + col) =
                make_float2(rnd_tf32(s_acc[nt][0]), rnd_tf32(s_acc[nt][1]));
            *reinterpret_cast<float2*>(Qs + (wm0 + g + 8) * ST + col) =
                make_float2(rnd_tf32(s_acc[nt][2]), rnd_tf32(s_acc[nt][3]));
        }
        __syncwarp();

        #pragma unroll
        for (int ks = 0; ks < 8; ks++) {
            const int k = ks * 8;
            uint32_t af[4], bf[8][2];
            const float* ap = Qs + (wm0 + g) * ST + k + tig;
            af[0] = __float_as_uint(ap[0]);
            af[1] = __float_as_uint(ap[8 * ST]);
            af[2] = __float_as_uint(ap[4]);
            af[3] = __float_as_uint(ap[8 * ST + 4]);
            #pragma unroll
            for (int nt = 0; nt < 8; nt++) {
                const float* bp = Vb + (nt * 8 + g) * ST + k + tig;
                bf[nt][0] = __float_as_uint(bp[0]);
                bf[nt][1] = __float_as_uint(bp[4]);
            }
            #pragma unroll
            for (int nt = 0; nt < 8; nt++)
                mma_tf32(acc_o[nt], af, bf[nt]);
        }
        __syncwarp();
    }

    float inv0 = 1.0f / l_r0, inv1 = 1.0f / l_r1;
    int r0 = m0 + wm0 + g, r1 = r0 + 8;
    float* c0 = ctx + ((size_t)b * SEQ + r0) * EMB + h * DK;
    float* c1 = ctx + ((size_t)b * SEQ + r1) * EMB + h * DK;
    #pragma unroll
    for (int nt = 0; nt < 8; nt++) {
        int col = nt * 8 + 2 * tig;
        if (r0 < SEQ)
            *reinterpret_cast<float2*>(c0 + col) =
                make_float2(rnd_tf32(acc_o[nt][0] * inv0), rnd_tf32(acc_o[nt][1] * inv0));
        if (r1 < SEQ)
            *reinterpret_cast<float2*>(c1 + col) =
                make_float2(rnd_tf32(acc_o[nt][2] * inv1), rnd_tf32(acc_o[nt][3] * inv1));
    }
}

// ---------------- LayerNorm (tf32-rounded output) -----------------------------
__global__ void __launch_bounds__(256) ln_kernel(
    const float* __restrict__ x, const float* __restrict__ g,
    const float* __restrict__ b, float* __restrict__ out)
{
    int row = blockIdx.x;
    const float* xr = x + (size_t)row * EMB;
    float* orow = out + (size_t)row * EMB;
    int tid = threadIdx.x;

    float v0 = xr[tid], v1 = xr[tid + 256], v2 = xr[tid + 512];
    float s = v0 + v1 + v2;
    __shared__ float red[8];
    #pragma unroll
    for (int o = 16; o; o >>= 1) s += __shfl_xor_sync(0xffffffffu, s, o);
    if ((tid & 31) == 0) red[tid >> 5] = s;
    __syncthreads();
    float tot = 0.f;
    #pragma unroll
    for (int i = 0; i < 8; i++) tot += red[i];
    float mu = tot * (1.0f / EMB);
    __syncthreads();
    float d0 = v0 - mu, d1 = v1 - mu, d2 = v2 - mu;
    float qv = d0 * d0 + d1 * d1 + d2 * d2;
    #pragma unroll
    for (int o = 16; o; o >>= 1) qv += __shfl_xor_sync(0xffffffffu, qv, o);
    if ((tid & 31) == 0) red[tid >> 5] = qv;
    __syncthreads();
    float tot2 = 0.f;
    #pragma unroll
    for (int i = 0; i < 8; i++) tot2 += red[i];
    float rstd = rsqrtf(tot2 * (1.0f / EMB) + 1e-5f);

    orow[tid]       = rnd_tf32(d0 * rstd * g[tid]       + b[tid]);
    orow[tid + 256] = rnd_tf32(d1 * rstd * g[tid + 256] + b[tid + 256]);
    orow[tid + 512] = rnd_tf32(d2 * rstd * g[tid + 512] + b[tid + 512]);
}

// ---------------- weight transpose + tf32 round -------------------------------
__global__ void __launch_bounds__(256) transpose_rnd(
    const float* __restrict__ in, float* __restrict__ out, int K, int N)
{
    __shared__ float t[32][33];
    int bx = blockIdx.x * 32;
    int by = blockIdx.y * 32;
    int tx = threadIdx.x & 31, ty = threadIdx.x >> 5;
    #pragma unroll
    for (int i = 0; i < 32; i += 8)
        t[ty + i][tx] = in[(size_t)(by + ty + i) * N + bx + tx];
    __syncthreads();
    #pragma unroll
    for (int i = 0; i < 32; i += 8)
        out[(size_t)(bx + ty + i) * K + by + tx] = rnd_tf32(t[tx][ty + i]);
}

// ---------------- v head transpose --------------------------------------------
__global__ void __launch_bounds__(256) vtrans_kernel(
    const float* __restrict__ qkv, float* __restrict__ vT)
{
    int z = blockIdx.z, b = z / HEADS, h = z % HEADS;
    int s0 = blockIdx.x * 32, d0 = blockIdx.y * 32;
    __shared__ float t[32][33];
    int tx = threadIdx.x & 31, ty = threadIdx.x >> 5;
    const float* src = qkv + (size_t)b * SEQ * QKVW + 2 * EMB + h * DK;
    #pragma unroll
    for (int i = 0; i < 32; i += 8) {
        int s = s0 + ty + i;
        t[ty + i][tx] = (s < SEQ) ? src[(size_t)s * QKVW + d0 + tx] : 0.f;
    }
    __syncthreads();
    float* dst = vT + ((size_t)z * DK + d0) * SEQP + s0;
    #pragma unroll
    for (int i = 0; i < 32; i += 8) {
        if (s0 + tx < SEQ) dst[(size_t)(ty + i) * SEQP + tx] = t[tx][ty + i];
    }
}

__global__ void concat_bias(const float* __restrict__ bq, const float* __restrict__ bk,
                            const float* __restrict__ bv, float* __restrict__ o)
{
    int i = blockIdx.x * 256 + threadIdx.x;
    if (i < EMB) { o[i] = bq[i]; o[i + EMB] = bk[i]; o[i + 2 * EMB] = bv[i]; }
}

// ---------------- host orchestration ------------------------------------------
extern "C" void kernel_launch(void* const* d_in, const int* in_sizes, int n_in,
                              void* d_out, int out_size)
{
    const float* x     = (const float*)d_in[0];
    const float* wq    = (const float*)d_in[1];
    const float* bq    = (const float*)d_in[2];
    const float* wk    = (const float*)d_in[3];
    const float* bk    = (const float*)d_in[4];
    const float* wv    = (const float*)d_in[5];
    const float* bv    = (const float*)d_in[6];
    const float* wo    = (const float*)d_in[7];
    const float* bo    = (const float*)d_in[8];
    const float* w1    = (const float*)d_in[9];
    const float* bf1   = (const float*)d_in[10];
    const float* w2    = (const float*)d_in[11];
    const float* bf2   = (const float*)d_in[12];
    const float* ln1_g = (const float*)d_in[13];
    const float* ln1_b = (const float*)d_in[14];
    const float* ln2_g = (const float*)d_in[15];
    const float* ln2_b = (const float*)d_in[16];
    float* out = (float*)d_out;

    float *h, *qkv, *vT, *ctx, *x2, *h2, *ff1;
    float *wqkvT, *woT, *w1T, *w2T, *bqkv;
    cudaGetSymbolAddress((void**)&h,     g_h);
    cudaGetSymbolAddress((void**)&qkv,   g_qkv);
    cudaGetSymbolAddress((void**)&vT,    g_vT);
    cudaGetSymbolAddress((void**)&ctx,   g_ctx);
    cudaGetSymbolAddress((void**)&x2,    g_x2);
    cudaGetSymbolAddress((void**)&h2,    g_h2);
    cudaGetSymbolAddress((void**)&ff1,   g_ff1);
    cudaGetSymbolAddress((void**)&wqkvT, g_wqkvT);
    cudaGetSymbolAddress((void**)&woT,   g_woT);
    cudaGetSymbolAddress((void**)&w1T,   g_w1T);
    cudaGetSymbolAddress((void**)&w2T,   g_w2T);
    cudaGetSymbolAddress((void**)&bqkv,  g_bqkv);

    const int SM128 = 2 * (128 + 128) * 36 * 4;          // 73728 (2-stage)
    const int SMFL  = (128 * 68 + 4 * 64 * 68) * 4;      // 104448
    cudaFuncSetAttribute(tcgemm<128, true,  false, false, true >, cudaFuncAttributeMaxDynamicSharedMemorySize, SM128);
    cudaFuncSetAttribute(tcgemm<128, true,  false, true,  false>, cudaFuncAttributeMaxDynamicSharedMemorySize, SM128);
    cudaFuncSetAttribute(tcgemm<128, true,  true,  false, true >, cudaFuncAttributeMaxDynamicSharedMemorySize, SM128);
    cudaFuncSetAttribute(flash_kernel, cudaFuncAttributeMaxDynamicSharedMemorySize, SMFL);

    const int M = NTOK;
    const int MT_ = (M + 127) / 128;       // 73
    const int ST_ = (SEQ + 127) / 128;     // 5

    // weight prep
    transpose_rnd<<<dim3(EMB / 32, EMB / 32), 256>>>(wq, wqkvT,                 EMB, EMB);
    transpose_rnd<<<dim3(EMB / 32, EMB / 32), 256>>>(wk, wqkvT + EMB * EMB,     EMB, EMB);
    transpose_rnd<<<dim3(EMB / 32, EMB / 32), 256>>>(wv, wqkvT + 2 * EMB * EMB, EMB, EMB);
    transpose_rnd<<<dim3(EMB / 32, EMB / 32), 256>>>(wo, woT, EMB, EMB);
    transpose_rnd<<<dim3(DFF / 32, EMB / 32), 256>>>(w1, w1T, EMB, DFF);
    transpose_rnd<<<dim3(EMB / 32, DFF / 32), 256>>>(w2, w2T, DFF, EMB);
    concat_bias<<<3, 256>>>(bq, bk, bv, bqkv);

    // LN1
    ln_kernel<<<M, 256>>>(x, ln1_g, ln1_b, h);

    // fused QKV
    tcgemm<128, true, false, false, true><<<dim3(QKVW / 128, MT_, 1), 256, SM128>>>(
        h, wqkvT, bqkv, nullptr, qkv, M, QKVW, EMB, EMB, EMB, QKVW);

    // v transpose per head
    vtrans_kernel<<<dim3((SEQ + 31) / 32, DK / 32, NBH), 256>>>(qkv, vT);

    // fused attention (scores + softmax + ctx)
    flash_kernel<<<dim3(ST_, NBH), 256, SMFL>>>(qkv, vT, ctx);

    // WO + bias + residual(x)
    tcgemm<128, true, false, true, false><<<dim3(EMB / 128, MT_, 1), 256, SM128>>>(
        ctx, woT, bo, x, x2, M, EMB, EMB, EMB, EMB, EMB);

    // LN2
    ln_kernel<<<M, 256>>>(x2, ln2_g, ln2_b, h2);

    // W1 + bias + GELU
    tcgemm<128, true, true, false, true><<<dim3(DFF / 128, MT_, 1), 256, SM128>>>(
        h2, w1T, bf1, nullptr, ff1, M, DFF, EMB, EMB, EMB, DFF);

    // W2 + bias + residual(x2) -> out
    tcgemm<128, true, false, true, false><<<dim3(EMB / 128, MT_, 1), 256, SM128>>>(
        ff1, w2T, bf2, x2, out, M, EMB, DFF, DFF, DFF, EMB);
}